// round 11
// baseline (speedup 1.0000x reference)
#include <cuda_runtime.h>

// ---------------------------------------------------------------------------
// GCN(D=256) x2 + MLP head, algebraically folded:
//   out = A( A (X Wfold) + c1*1 ) + bc ,  Wfold = W1^T W2^T Wm1^T Wm2^T [256x5]
// A = D^{-1/2}(Adj+I)D^{-1/2}; dinv factored out of edge kernels.
// R11: redux.f32 unsupported on sm_103 -> split-channel shuffle reduction:
//      after the offset-16 butterfly stage the two 16-lane halves carry
//      channels {0,1,2} / {3,4} in shared registers, so the remaining 4
//      stages shuffle only 3 regs: 17 SHFL/node instead of 25.
//      Rest unchanged from R9 (best passing: 168.4us).
// ---------------------------------------------------------------------------

#define Dd 256
#define Hh 128
#define Cc 5
#define Ss 8           // padded row stride (32B rows -> 1 L2 sector)
#define NMAX 100352
#define FOLD_BLOCKS 16
#define GEMV_BLOCKS 1184

__device__ float g_deg[NMAX];        // raw degree (self-loop included)
__device__ float g_bufA[NMAX * Ss];  // z' (=dinv*z), then q (=dinv*p)
__device__ float g_bufB[NMAX * Ss];  // edge-sum accumulator (both passes)
__device__ float g_M1[Dd * Cc];      // fold stage-1 intermediate
__device__ float g_WcT[Dd * Cc];     // fold stage-2 intermediate
__device__ float g_Wc[Cc * Dd];      // folded weight, channel-major [c][k]
__device__ float g_c1[Cc];
__device__ float g_bc[Cc];
__device__ unsigned g_bar;           // fold grid-barrier counter (reset per launch)

__global__ void init_kernel(int n) {
    int i = blockIdx.x * blockDim.x + threadIdx.x;
    if (i < n) {
        g_deg[i] = 1.0f;  // self-loop contributes 1 to degree
        float4 z = make_float4(0.f, 0.f, 0.f, 0.f);
        ((float4*)g_bufB)[i * 2 + 0] = z;
        ((float4*)g_bufB)[i * 2 + 1] = z;
    }
    if (i == 0) g_bar = 0u;
}

__global__ void deg_kernel(const int* __restrict__ dst, int E) {
    int t = blockIdx.x * blockDim.x + threadIdx.x;
    int e0 = t * 4;
    if (e0 + 3 < E) {
        int4 d = __ldg((const int4*)(dst + e0));
        atomicAdd(&g_deg[d.x], 1.0f);
        atomicAdd(&g_deg[d.y], 1.0f);
        atomicAdd(&g_deg[d.z], 1.0f);
        atomicAdd(&g_deg[d.w], 1.0f);
    } else {
        for (int e = e0; e < E; ++e) atomicAdd(&g_deg[__ldg(dst + e)], 1.0f);
    }
}

// Spin grid barrier for the fold kernel (FOLD_BLOCKS co-resident blocks).
__device__ __forceinline__ void fold_gbar(unsigned target) {
    __syncthreads();
    if (threadIdx.x == 0) {
        asm volatile("red.release.gpu.global.add.u32 [%0], 1;"
                     :: "l"(&g_bar) : "memory");
        unsigned v;
        do {
            asm volatile("ld.acquire.gpu.global.u32 %0, [%1];"
                         : "=r"(v) : "l"(&g_bar) : "memory");
        } while (v < target);
    }
    __syncthreads();
}

// Fused fold: M1 = Wm1^T Wm2^T ; WcT = W2^T M1 ; Wfold = W1^T WcT ; biases.
__global__ void fold_kernel(const float* __restrict__ W1, const float* __restrict__ b1,
                            const float* __restrict__ W2, const float* __restrict__ b2,
                            const float* __restrict__ Wm1, const float* __restrict__ bm1,
                            const float* __restrict__ Wm2, const float* __restrict__ bm2) {
    __shared__ float red[256 * Cc];
    __shared__ float st[Hh];
    int t = threadIdx.x;
    int rloc = t & 15, part = t >> 4;      // 16 rows/block, 16 k-parts
    int r = blockIdx.x * 16 + rloc;

    // Phase A: M1[r][c] = sum_h Wm1[h,r] * Wm2[c,h]   (h = 128)
    {
        float acc[Cc] = {};
        for (int h = part * 8; h < part * 8 + 8; ++h) {
            float a = Wm1[h * Dd + r];
            #pragma unroll
            for (int c = 0; c < Cc; ++c) acc[c] += a * Wm2[c * Hh + h];
        }
        #pragma unroll
        for (int c = 0; c < Cc; ++c) red[t * Cc + c] = acc[c];
        __syncthreads();
        if (part == 0) {
            float s[Cc] = {};
            for (int p = 0; p < 16; ++p)
                #pragma unroll
                for (int c = 0; c < Cc; ++c) s[c] += red[(p * 16 + rloc) * Cc + c];
            #pragma unroll
            for (int c = 0; c < Cc; ++c) g_M1[r * Cc + c] = s[c];
        }
    }
    fold_gbar(FOLD_BLOCKS);

    // Phase B: WcT[r][c] = sum_k W2[k,r] * M1[k][c]   (k = 256)
    {
        float acc[Cc] = {};
        for (int k = part * 16; k < part * 16 + 16; ++k) {
            float a = W2[k * Dd + r];
            #pragma unroll
            for (int c = 0; c < Cc; ++c) acc[c] += a * g_M1[k * Cc + c];
        }
        #pragma unroll
        for (int c = 0; c < Cc; ++c) red[t * Cc + c] = acc[c];
        __syncthreads();
        if (part == 0) {
            float s[Cc] = {};
            for (int p = 0; p < 16; ++p)
                #pragma unroll
                for (int c = 0; c < Cc; ++c) s[c] += red[(p * 16 + rloc) * Cc + c];
            #pragma unroll
            for (int c = 0; c < Cc; ++c) g_WcT[r * Cc + c] = s[c];
        }
    }
    fold_gbar(2 * FOLD_BLOCKS);

    // Phase C: Wfold[r][c] = sum_k W1[k,r] * WcT[k][c]  -> channel-major g_Wc
    {
        float acc[Cc] = {};
        for (int k = part * 16; k < part * 16 + 16; ++k) {
            float a = W1[k * Dd + r];
            #pragma unroll
            for (int c = 0; c < Cc; ++c) acc[c] += a * g_WcT[k * Cc + c];
        }
        #pragma unroll
        for (int c = 0; c < Cc; ++c) red[t * Cc + c] = acc[c];
        __syncthreads();
        if (part == 0) {
            float s[Cc] = {};
            for (int p = 0; p < 16; ++p)
                #pragma unroll
                for (int c = 0; c < Cc; ++c) s[c] += red[(p * 16 + rloc) * Cc + c];
            #pragma unroll
            for (int c = 0; c < Cc; ++c) g_Wc[c * Dd + r] = s[c];
        }
    }

    // Phase D (block 0 only): c1 = b1 @ WcT ; bc = Wm2 (Wm1 b2 + bm1) + bm2
    if (blockIdx.x == 0) {
        __syncthreads();
        int w = t >> 5, lane = t & 31;     // 8 warps
        for (int i = 0; i < 16; ++i) {
            int h = w * 16 + i;
            float s = 0.f;
            for (int d = lane; d < Dd; d += 32) s += Wm1[h * Dd + d] * b2[d];
            #pragma unroll
            for (int off = 16; off; off >>= 1) s += __shfl_xor_sync(0xFFFFFFFFu, s, off);
            if (lane == 0) st[h] = s + bm1[h];
        }
        __syncthreads();
        if (w < Cc) {
            float s1 = 0.f;
            for (int d = lane; d < Dd; d += 32) s1 += b1[d] * g_WcT[d * Cc + w];
            #pragma unroll
            for (int off = 16; off; off >>= 1) s1 += __shfl_xor_sync(0xFFFFFFFFu, s1, off);
            if (lane == 0) g_c1[w] = s1;
            float s2 = 0.f;
            for (int h = lane; h < Hh; h += 32) s2 += Wm2[w * Hh + h] * st[h];
            #pragma unroll
            for (int off = 16; off; off >>= 1) s2 += __shfl_xor_sync(0xFFFFFFFFu, s2, off);
            if (lane == 0) g_bc[w] = s2 + bm2[w];
        }
    }
}

// z' = dinv * (X @ Wfold): grid-stride warp-per-node; weights in registers;
// split-channel warp reduction (17 SHFL/node).
__global__ void gemv_kernel(const float* __restrict__ x, int n) {
    int lane = threadIdx.x & 31;
    bool low = lane < 16;
    // wreg[it][j][c]: weight for x-element (it*32+lane)*4+j, channel c
    float wreg[2][4][Cc];
    #pragma unroll
    for (int it = 0; it < 2; ++it) {
        int base = (it * 32 + lane) * 4;
        #pragma unroll
        for (int j = 0; j < 4; ++j)
            #pragma unroll
            for (int c = 0; c < Cc; ++c)
                wreg[it][j][c] = __ldg(&g_Wc[c * Dd + base + j]);
    }
    int nwarps = (GEMV_BLOCKS * 256) >> 5;
    int gw0 = (blockIdx.x * blockDim.x + threadIdx.x) >> 5;
    for (int gw = gw0; gw < n; gw += nwarps) {
        const float4* xr = (const float4*)x + (size_t)gw * (Dd / 4);
        float a0 = 0.f, a1 = 0.f, a2 = 0.f, a3 = 0.f, a4 = 0.f;
        #pragma unroll
        for (int it = 0; it < 2; ++it) {
            float4 v = xr[it * 32 + lane];
            a0 += v.x*wreg[it][0][0] + v.y*wreg[it][1][0] + v.z*wreg[it][2][0] + v.w*wreg[it][3][0];
            a1 += v.x*wreg[it][0][1] + v.y*wreg[it][1][1] + v.z*wreg[it][2][1] + v.w*wreg[it][3][1];
            a2 += v.x*wreg[it][0][2] + v.y*wreg[it][1][2] + v.z*wreg[it][2][2] + v.w*wreg[it][3][2];
            a3 += v.x*wreg[it][0][3] + v.y*wreg[it][1][3] + v.z*wreg[it][2][3] + v.w*wreg[it][3][3];
            a4 += v.x*wreg[it][0][4] + v.y*wreg[it][1][4] + v.z*wreg[it][2][4] + v.w*wreg[it][3][4];
        }
        // Stage 1 (offset 16): pair-sums over {l, l^16}; both halves now hold
        // identical pair data, so channels split across halves.
        a0 += __shfl_xor_sync(0xFFFFFFFFu, a0, 16);
        a1 += __shfl_xor_sync(0xFFFFFFFFu, a1, 16);
        a2 += __shfl_xor_sync(0xFFFFFFFFu, a2, 16);
        a3 += __shfl_xor_sync(0xFFFFFFFFu, a3, 16);
        a4 += __shfl_xor_sync(0xFFFFFFFFu, a4, 16);
        float v0 = low ? a0 : a3;
        float v1 = low ? a1 : a4;
        float v2 = a2;                 // live only in low half
        // Stages 8,4,2,1 within 16-lane halves: 3 regs only.
        #pragma unroll
        for (int off = 8; off; off >>= 1) {
            v0 += __shfl_xor_sync(0xFFFFFFFFu, v0, off);
            v1 += __shfl_xor_sync(0xFFFFFFFFu, v1, off);
            v2 += __shfl_xor_sync(0xFFFFFFFFu, v2, off);
        }
        // lane 0: v0=S0 v1=S1 v2=S2 ; lane 16: v0=S3 v1=S4
        if (lane == 0) {
            float w = rsqrtf(g_deg[gw]);
            float* o = &g_bufA[(size_t)gw * Ss];
            o[0] = w * v0; o[1] = w * v1; o[2] = w * v2;
        } else if (lane == 16) {
            float w = rsqrtf(g_deg[gw]);
            float* o = &g_bufA[(size_t)gw * Ss];
            o[3] = w * v0; o[4] = w * v1;
        }
    }
}

__device__ __forceinline__ void red_row(int d, float4 a, float a4) {
    float* vd = &g_bufB[(size_t)d * Ss];
    unsigned long long gp = __cvta_generic_to_global(vd);
    asm volatile("red.global.add.v4.f32 [%0], {%1, %2, %3, %4};"
                 :: "l"(gp), "f"(a.x), "f"(a.y), "f"(a.z), "f"(a.w) : "memory");
    atomicAdd(vd + 4, a4);
}

// Edge pass: bufB[dst] += bufA[src], 2 edges per thread (best measured form).
__global__ void agg_kernel(const int* __restrict__ src, const int* __restrict__ dst, int E) {
    int t = blockIdx.x * blockDim.x + threadIdx.x;
    int e0 = t * 2;
    if (e0 + 1 < E) {
        int2 s = __ldg((const int2*)(src + e0));
        int2 d = __ldg((const int2*)(dst + e0));
        const float* vs0 = &g_bufA[(size_t)s.x * Ss];
        const float* vs1 = &g_bufA[(size_t)s.y * Ss];
        float4 a = *(const float4*)vs0;
        float4 b = *(const float4*)vs1;
        float a4 = vs0[4];
        float b4 = vs1[4];
        red_row(d.x, a, a4);
        red_row(d.y, b, b4);
    } else if (e0 < E) {
        int s = __ldg(src + e0);
        int d = __ldg(dst + e0);
        const float* vs = &g_bufA[(size_t)s * Ss];
        red_row(d, *(const float4*)vs, vs[4]);
    }
}

// After pass 1: p = dinv*(S1 + z') + c1 ;  q = dinv*p -> bufA; reset bufB.
__global__ void fin1_kernel(int n) {
    int i = blockIdx.x * blockDim.x + threadIdx.x;
    if (i >= n) return;
    float w = rsqrtf(g_deg[i]);
    float4 sB = *(const float4*)&g_bufB[i * Ss];
    float  sB4 = g_bufB[i * Ss + 4];
    float4 zA = *(const float4*)&g_bufA[i * Ss];
    float  zA4 = g_bufA[i * Ss + 4];
    float4 q;
    q.x = w * (w * (sB.x + zA.x) + g_c1[0]);
    q.y = w * (w * (sB.y + zA.y) + g_c1[1]);
    q.z = w * (w * (sB.z + zA.z) + g_c1[2]);
    q.w = w * (w * (sB.w + zA.w) + g_c1[3]);
    float q4 = w * (w * (sB4 + zA4) + g_c1[4]);
    *(float4*)&g_bufA[i * Ss] = q;
    g_bufA[i * Ss + 4] = q4;
    *(float4*)&g_bufB[i * Ss] = make_float4(0.f, 0.f, 0.f, 0.f);
    g_bufB[i * Ss + 4] = 0.f;
}

// After pass 2: out = dinv*(S2 + q) + bc
__global__ void fin2_kernel(float* __restrict__ out, int n) {
    int i = blockIdx.x * blockDim.x + threadIdx.x;
    if (i >= n) return;
    float w = rsqrtf(g_deg[i]);
    float4 sB = *(const float4*)&g_bufB[i * Ss];
    float  sB4 = g_bufB[i * Ss + 4];
    float4 qA = *(const float4*)&g_bufA[i * Ss];
    float  qA4 = g_bufA[i * Ss + 4];
    float* o = out + (size_t)i * Cc;
    o[0] = w * (sB.x + qA.x) + g_bc[0];
    o[1] = w * (sB.y + qA.y) + g_bc[1];
    o[2] = w * (sB.z + qA.z) + g_bc[2];
    o[3] = w * (sB.w + qA.w) + g_bc[3];
    o[4] = w * (sB4 + qA4) + g_bc[4];
}

extern "C" void kernel_launch(void* const* d_in, const int* in_sizes, int n_in,
                              void* d_out, int out_size) {
    const float* x   = (const float*)d_in[0];
    const int*   ei  = (const int*)d_in[1];
    const float* W1  = (const float*)d_in[2];
    const float* b1  = (const float*)d_in[3];
    const float* W2  = (const float*)d_in[4];
    const float* b2  = (const float*)d_in[5];
    const float* Wm1 = (const float*)d_in[6];
    const float* bm1 = (const float*)d_in[7];
    const float* Wm2 = (const float*)d_in[8];
    const float* bm2 = (const float*)d_in[9];
    float* out = (float*)d_out;

    int n = in_sizes[0] / Dd;
    int E = in_sizes[1] / 2;
    const int* src = ei;
    const int* dst = ei + E;

    int nb  = (n + 255) / 256;
    int eb4 = ((E + 3) / 4 + 255) / 256;   // 4 edges/thread (deg)
    int eb2 = ((E + 1) / 2 + 255) / 256;   // 2 edges/thread (agg)

    init_kernel<<<nb, 256>>>(n);
    deg_kernel<<<eb4, 256>>>(dst, E);
    fold_kernel<<<FOLD_BLOCKS, 256>>>(W1, b1, W2, b2, Wm1, bm1, Wm2, bm2);
    gemv_kernel<<<GEMV_BLOCKS, 256>>>(x, n);
    agg_kernel<<<eb2, 256>>>(src, dst, E);   // pass 1
    fin1_kernel<<<nb, 256>>>(n);
    agg_kernel<<<eb2, 256>>>(src, dst, E);   // pass 2
    fin2_kernel<<<nb, 256>>>(out, n);
}

// round 12
// speedup vs baseline: 1.1536x; 1.1536x over previous
#include <cuda_runtime.h>

// ---------------------------------------------------------------------------
// GCN(D=256) x2 + MLP head, algebraically folded:
//   out = A( A (X Wfold) + c1*1 ) + bc ,  Wfold = W1^T W2^T Wm1^T Wm2^T [256x5]
// A = D^{-1/2}(Adj+I)D^{-1/2}.
// R12: megakernel overlap — one launch runs {fold (blocks 0..15), degree
//      count (next DB blocks), gemv (rest, spins on a release/acquire flag
//      until fold is done; writes RAW z)}. A cheap scale kernel then applies
//      dinv to bufA. Edge engine & fin kernels unchanged (measured floors).
// ---------------------------------------------------------------------------

#define Dd 256
#define Hh 128
#define Cc 5
#define Ss 8           // padded row stride (32B rows -> 1 L2 sector)
#define NMAX 100352
#define FOLD_BLOCKS 16
#define GEMV_BLOCKS 1184

__device__ int   g_cnt[NMAX];        // edge in-degree (self-loop excluded)
__device__ float g_bufA[NMAX * Ss];  // z (raw), then dinv*z, then q
__device__ float g_bufB[NMAX * Ss];  // edge-sum accumulator (both passes)
__device__ float g_M1[Dd * Cc];      // fold stage-1 intermediate
__device__ float g_WcT[Dd * Cc];     // fold stage-2 intermediate
__device__ float g_Wc[Cc * Dd];      // folded weight, channel-major [c][k]
__device__ float g_c1[Cc];
__device__ float g_bc[Cc];
__device__ unsigned g_bar;           // fold grid-barrier counter
__device__ unsigned g_done;          // fold-completion flag

__global__ void init_kernel(int n) {
    int i = blockIdx.x * blockDim.x + threadIdx.x;
    if (i < n) {
        g_cnt[i] = 0;
        float4 z = make_float4(0.f, 0.f, 0.f, 0.f);
        ((float4*)g_bufB)[i * 2 + 0] = z;
        ((float4*)g_bufB)[i * 2 + 1] = z;
    }
    if (i == 0) { g_bar = 0u; g_done = 0u; }
}

// Spin grid barrier among the FOLD_BLOCKS fold blocks.
__device__ __forceinline__ void fold_gbar(unsigned target) {
    __syncthreads();
    if (threadIdx.x == 0) {
        asm volatile("red.release.gpu.global.add.u32 [%0], 1;"
                     :: "l"(&g_bar) : "memory");
        unsigned v;
        do {
            asm volatile("ld.acquire.gpu.global.u32 %0, [%1];"
                         : "=r"(v) : "l"(&g_bar) : "memory");
        } while (v < target);
    }
    __syncthreads();
}

__device__ void do_fold(const float* __restrict__ W1, const float* __restrict__ b1,
                        const float* __restrict__ W2, const float* __restrict__ b2,
                        const float* __restrict__ Wm1, const float* __restrict__ bm1,
                        const float* __restrict__ Wm2, const float* __restrict__ bm2) {
    __shared__ float red[256 * Cc];
    __shared__ float st[Hh];
    int t = threadIdx.x;
    int rloc = t & 15, part = t >> 4;      // 16 rows/block, 16 k-parts
    int r = blockIdx.x * 16 + rloc;

    // Phase A: M1[r][c] = sum_h Wm1[h,r] * Wm2[c,h]
    {
        float acc[Cc] = {};
        for (int h = part * 8; h < part * 8 + 8; ++h) {
            float a = Wm1[h * Dd + r];
            #pragma unroll
            for (int c = 0; c < Cc; ++c) acc[c] += a * Wm2[c * Hh + h];
        }
        #pragma unroll
        for (int c = 0; c < Cc; ++c) red[t * Cc + c] = acc[c];
        __syncthreads();
        if (part == 0) {
            float s[Cc] = {};
            for (int p = 0; p < 16; ++p)
                #pragma unroll
                for (int c = 0; c < Cc; ++c) s[c] += red[(p * 16 + rloc) * Cc + c];
            #pragma unroll
            for (int c = 0; c < Cc; ++c) g_M1[r * Cc + c] = s[c];
        }
    }
    fold_gbar(FOLD_BLOCKS);

    // Phase B: WcT[r][c] = sum_k W2[k,r] * M1[k][c]
    {
        float acc[Cc] = {};
        for (int k = part * 16; k < part * 16 + 16; ++k) {
            float a = W2[k * Dd + r];
            #pragma unroll
            for (int c = 0; c < Cc; ++c) acc[c] += a * g_M1[k * Cc + c];
        }
        #pragma unroll
        for (int c = 0; c < Cc; ++c) red[t * Cc + c] = acc[c];
        __syncthreads();
        if (part == 0) {
            float s[Cc] = {};
            for (int p = 0; p < 16; ++p)
                #pragma unroll
                for (int c = 0; c < Cc; ++c) s[c] += red[(p * 16 + rloc) * Cc + c];
            #pragma unroll
            for (int c = 0; c < Cc; ++c) g_WcT[r * Cc + c] = s[c];
        }
    }
    fold_gbar(2 * FOLD_BLOCKS);

    // Phase C: Wfold[r][c] = sum_k W1[k,r] * WcT[k][c]  -> channel-major g_Wc
    {
        float acc[Cc] = {};
        for (int k = part * 16; k < part * 16 + 16; ++k) {
            float a = W1[k * Dd + r];
            #pragma unroll
            for (int c = 0; c < Cc; ++c) acc[c] += a * g_WcT[k * Cc + c];
        }
        #pragma unroll
        for (int c = 0; c < Cc; ++c) red[t * Cc + c] = acc[c];
        __syncthreads();
        if (part == 0) {
            float s[Cc] = {};
            for (int p = 0; p < 16; ++p)
                #pragma unroll
                for (int c = 0; c < Cc; ++c) s[c] += red[(p * 16 + rloc) * Cc + c];
            #pragma unroll
            for (int c = 0; c < Cc; ++c) g_Wc[c * Dd + r] = s[c];
        }
    }
    fold_gbar(3 * FOLD_BLOCKS);   // all phase-C writes globally published

    // Publish fold completion (block 0); gemv blocks acquire on g_done.
    if (blockIdx.x == 0 && threadIdx.x == 0) {
        asm volatile("st.release.gpu.global.u32 [%0], 1;"
                     :: "l"(&g_done) : "memory");
    }

    // Phase D (block 0): c1 = b1 @ WcT ; bc = Wm2 (Wm1 b2 + bm1) + bm2
    if (blockIdx.x == 0) {
        int w = t >> 5, lane = t & 31;
        for (int i = 0; i < 16; ++i) {
            int h = w * 16 + i;
            float s = 0.f;
            for (int d = lane; d < Dd; d += 32) s += Wm1[h * Dd + d] * b2[d];
            #pragma unroll
            for (int off = 16; off; off >>= 1) s += __shfl_xor_sync(0xFFFFFFFFu, s, off);
            if (lane == 0) st[h] = s + bm1[h];
        }
        __syncthreads();
        if (w < Cc) {
            float s1 = 0.f;
            for (int d = lane; d < Dd; d += 32) s1 += b1[d] * g_WcT[d * Cc + w];
            #pragma unroll
            for (int off = 16; off; off >>= 1) s1 += __shfl_xor_sync(0xFFFFFFFFu, s1, off);
            if (lane == 0) g_c1[w] = s1;
            float s2 = 0.f;
            for (int h = lane; h < Hh; h += 32) s2 += Wm2[w * Hh + h] * st[h];
            #pragma unroll
            for (int off = 16; off; off >>= 1) s2 += __shfl_xor_sync(0xFFFFFFFFu, s2, off);
            if (lane == 0) g_bc[w] = s2 + bm2[w];
        }
    }
}

__device__ void do_deg(const int* __restrict__ dst, int E, int blk) {
    int t = blk * blockDim.x + threadIdx.x;
    int e0 = t * 4;
    if (e0 + 3 < E) {
        int4 d = __ldg((const int4*)(dst + e0));
        atomicAdd(&g_cnt[d.x], 1);
        atomicAdd(&g_cnt[d.y], 1);
        atomicAdd(&g_cnt[d.z], 1);
        atomicAdd(&g_cnt[d.w], 1);
    } else {
        for (int e = e0; e < E; ++e) atomicAdd(&g_cnt[__ldg(dst + e)], 1);
    }
}

// gemv: raw z = X @ Wfold (NO dinv); weights in registers; 25-SHFL butterfly.
__device__ void do_gemv(const float* __restrict__ x, int n, int blk) {
    // wait for fold (release/acquire on g_done; cumulativity covers all
    // fold blocks' phase-C writes published through the g_bar chain)
    if (threadIdx.x == 0) {
        unsigned v;
        do {
            asm volatile("ld.acquire.gpu.global.u32 %0, [%1];"
                         : "=r"(v) : "l"(&g_done) : "memory");
        } while (v == 0u);
    }
    __syncthreads();

    int lane = threadIdx.x & 31;
    float wreg[2][4][Cc];
    #pragma unroll
    for (int it = 0; it < 2; ++it) {
        int base = (it * 32 + lane) * 4;
        #pragma unroll
        for (int j = 0; j < 4; ++j)
            #pragma unroll
            for (int c = 0; c < Cc; ++c)
                wreg[it][j][c] = g_Wc[c * Dd + base + j];
    }
    int nwarps = (GEMV_BLOCKS * 256) >> 5;
    int gw0 = (blk * 256 + threadIdx.x) >> 5;
    for (int gw = gw0; gw < n; gw += nwarps) {
        const float4* xr = (const float4*)x + (size_t)gw * (Dd / 4);
        float a0 = 0.f, a1 = 0.f, a2 = 0.f, a3 = 0.f, a4 = 0.f;
        #pragma unroll
        for (int it = 0; it < 2; ++it) {
            float4 v = xr[it * 32 + lane];
            a0 += v.x*wreg[it][0][0] + v.y*wreg[it][1][0] + v.z*wreg[it][2][0] + v.w*wreg[it][3][0];
            a1 += v.x*wreg[it][0][1] + v.y*wreg[it][1][1] + v.z*wreg[it][2][1] + v.w*wreg[it][3][1];
            a2 += v.x*wreg[it][0][2] + v.y*wreg[it][1][2] + v.z*wreg[it][2][2] + v.w*wreg[it][3][2];
            a3 += v.x*wreg[it][0][3] + v.y*wreg[it][1][3] + v.z*wreg[it][2][3] + v.w*wreg[it][3][3];
            a4 += v.x*wreg[it][0][4] + v.y*wreg[it][1][4] + v.z*wreg[it][2][4] + v.w*wreg[it][3][4];
        }
        #pragma unroll
        for (int off = 16; off; off >>= 1) {
            a0 += __shfl_xor_sync(0xFFFFFFFFu, a0, off);
            a1 += __shfl_xor_sync(0xFFFFFFFFu, a1, off);
            a2 += __shfl_xor_sync(0xFFFFFFFFu, a2, off);
            a3 += __shfl_xor_sync(0xFFFFFFFFu, a3, off);
            a4 += __shfl_xor_sync(0xFFFFFFFFu, a4, off);
        }
        if (lane == 0) {
            float* o = &g_bufA[(size_t)gw * Ss];
            o[0] = a0; o[1] = a1; o[2] = a2; o[3] = a3; o[4] = a4;
        }
    }
}

// Megakernel: block role by blockIdx.x.
__global__ void __launch_bounds__(256) mega_kernel(
    const float* __restrict__ x, int n,
    const int* __restrict__ dst, int E, int degBlocks,
    const float* __restrict__ W1, const float* __restrict__ b1,
    const float* __restrict__ W2, const float* __restrict__ b2,
    const float* __restrict__ Wm1, const float* __restrict__ bm1,
    const float* __restrict__ Wm2, const float* __restrict__ bm2) {
    int b = blockIdx.x;
    if (b < FOLD_BLOCKS) {
        do_fold(W1, b1, W2, b2, Wm1, bm1, Wm2, bm2);
    } else if (b < FOLD_BLOCKS + degBlocks) {
        do_deg(dst, E, b - FOLD_BLOCKS);
    } else {
        do_gemv(x, n, b - FOLD_BLOCKS - degBlocks);
    }
}

// Apply dinv to z: bufA *= rsqrt(cnt+1) per row.
__global__ void scale_kernel(int n) {
    int i = blockIdx.x * blockDim.x + threadIdx.x;
    if (i >= n) return;
    float w = rsqrtf((float)(g_cnt[i] + 1));
    float4 v = *(const float4*)&g_bufA[i * Ss];
    float  v4 = g_bufA[i * Ss + 4];
    v.x *= w; v.y *= w; v.z *= w; v.w *= w;
    *(float4*)&g_bufA[i * Ss] = v;
    g_bufA[i * Ss + 4] = w * v4;
}

__device__ __forceinline__ void red_row(int d, float4 a, float a4) {
    float* vd = &g_bufB[(size_t)d * Ss];
    unsigned long long gp = __cvta_generic_to_global(vd);
    asm volatile("red.global.add.v4.f32 [%0], {%1, %2, %3, %4};"
                 :: "l"(gp), "f"(a.x), "f"(a.y), "f"(a.z), "f"(a.w) : "memory");
    atomicAdd(vd + 4, a4);
}

// Edge pass: bufB[dst] += bufA[src], 2 edges per thread (best measured form).
__global__ void agg_kernel(const int* __restrict__ src, const int* __restrict__ dst, int E) {
    int t = blockIdx.x * blockDim.x + threadIdx.x;
    int e0 = t * 2;
    if (e0 + 1 < E) {
        int2 s = __ldg((const int2*)(src + e0));
        int2 d = __ldg((const int2*)(dst + e0));
        const float* vs0 = &g_bufA[(size_t)s.x * Ss];
        const float* vs1 = &g_bufA[(size_t)s.y * Ss];
        float4 a = *(const float4*)vs0;
        float4 b = *(const float4*)vs1;
        float a4 = vs0[4];
        float b4 = vs1[4];
        red_row(d.x, a, a4);
        red_row(d.y, b, b4);
    } else if (e0 < E) {
        int s = __ldg(src + e0);
        int d = __ldg(dst + e0);
        const float* vs = &g_bufA[(size_t)s * Ss];
        red_row(d, *(const float4*)vs, vs[4]);
    }
}

// After pass 1: p = dinv*(S1 + z') + c1 ;  q = dinv*p -> bufA; reset bufB.
__global__ void fin1_kernel(int n) {
    int i = blockIdx.x * blockDim.x + threadIdx.x;
    if (i >= n) return;
    float w = rsqrtf((float)(g_cnt[i] + 1));
    float4 sB = *(const float4*)&g_bufB[i * Ss];
    float  sB4 = g_bufB[i * Ss + 4];
    float4 zA = *(const float4*)&g_bufA[i * Ss];
    float  zA4 = g_bufA[i * Ss + 4];
    float4 q;
    q.x = w * (w * (sB.x + zA.x) + g_c1[0]);
    q.y = w * (w * (sB.y + zA.y) + g_c1[1]);
    q.z = w * (w * (sB.z + zA.z) + g_c1[2]);
    q.w = w * (w * (sB.w + zA.w) + g_c1[3]);
    float q4 = w * (w * (sB4 + zA4) + g_c1[4]);
    *(float4*)&g_bufA[i * Ss] = q;
    g_bufA[i * Ss + 4] = q4;
    *(float4*)&g_bufB[i * Ss] = make_float4(0.f, 0.f, 0.f, 0.f);
    g_bufB[i * Ss + 4] = 0.f;
}

// After pass 2: out = dinv*(S2 + q) + bc
__global__ void fin2_kernel(float* __restrict__ out, int n) {
    int i = blockIdx.x * blockDim.x + threadIdx.x;
    if (i >= n) return;
    float w = rsqrtf((float)(g_cnt[i] + 1));
    float4 sB = *(const float4*)&g_bufB[i * Ss];
    float  sB4 = g_bufB[i * Ss + 4];
    float4 qA = *(const float4*)&g_bufA[i * Ss];
    float  qA4 = g_bufA[i * Ss + 4];
    float* o = out + (size_t)i * Cc;
    o[0] = w * (sB.x + qA.x) + g_bc[0];
    o[1] = w * (sB.y + qA.y) + g_bc[1];
    o[2] = w * (sB.z + qA.z) + g_bc[2];
    o[3] = w * (sB.w + qA.w) + g_bc[3];
    o[4] = w * (sB4 + qA4) + g_bc[4];
}

extern "C" void kernel_launch(void* const* d_in, const int* in_sizes, int n_in,
                              void* d_out, int out_size) {
    const float* x   = (const float*)d_in[0];
    const int*   ei  = (const int*)d_in[1];
    const float* W1  = (const float*)d_in[2];
    const float* b1  = (const float*)d_in[3];
    const float* W2  = (const float*)d_in[4];
    const float* b2  = (const float*)d_in[5];
    const float* Wm1 = (const float*)d_in[6];
    const float* bm1 = (const float*)d_in[7];
    const float* Wm2 = (const float*)d_in[8];
    const float* bm2 = (const float*)d_in[9];
    float* out = (float*)d_out;

    int n = in_sizes[0] / Dd;
    int E = in_sizes[1] / 2;
    const int* src = ei;
    const int* dst = ei + E;

    int nb  = (n + 255) / 256;
    int degBlocks = ((E + 3) / 4 + 255) / 256;   // 4 edges/thread
    int eb2 = ((E + 1) / 2 + 255) / 256;         // 2 edges/thread (agg)
    int megaBlocks = FOLD_BLOCKS + degBlocks + GEMV_BLOCKS;

    init_kernel<<<nb, 256>>>(n);
    mega_kernel<<<megaBlocks, 256>>>(x, n, dst, E, degBlocks,
                                     W1, b1, W2, b2, Wm1, bm1, Wm2, bm2);
    scale_kernel<<<nb, 256>>>(n);
    agg_kernel<<<eb2, 256>>>(src, dst, E);   // pass 1
    fin1_kernel<<<nb, 256>>>(n);
    agg_kernel<<<eb2, 256>>>(src, dst, E);   // pass 2
    fin2_kernel<<<nb, 256>>>(out, n);
}